// round 13
// baseline (speedup 1.0000x reference)
#include <cuda_runtime.h>
#include <math.h>

#define B_  2
#define N_  8
#define K_  8
#define C_  256
#define HW_ 9216
#define BN_ (B_*N_)
#define PX_ 32                      // pixels per readout tile

// ---------------- scratch (__device__ globals: no allocation allowed) -------
__device__ float d_wsum[BN_*C_];       // sum(value*mask) over HW
__device__ float d_vsum[BN_*C_];       // sum(value) over HW
__device__ float d_msum[BN_];          // sum(mask) over HW
__device__ float d_bnn [BN_*K_*C_];    // l2norm(proto_new)
__device__ float d_pscale[BN_*K_];     // proto_new = bnn * pscale
__device__ float d_vldn[BN_*K_];       // valid_new as float
__device__ int   d_anyv[BN_];          // any(valid_new)

__device__ __forceinline__ float warpSum(float v) {
    #pragma unroll
    for (int o = 16; o; o >>= 1) v += __shfl_xor_sync(0xffffffffu, v, o);
    return v;
}
__device__ __forceinline__ float warpMax(float v) {
    #pragma unroll
    for (int o = 16; o; o >>= 1) v = fmaxf(v, __shfl_xor_sync(0xffffffffu, v, o));
    return v;
}

// ---------------- kernel 1: masked pooling sums over HW (+ msum) -----------
// grid (C, N, B), 256 threads. Reads full value once (~5.3 TB/s measured).
__global__ void __launch_bounds__(256) k_candsum(const float* __restrict__ value,
                                                 const float* __restrict__ mask) {
    int c  = blockIdx.x;
    int bn = blockIdx.z * N_ + blockIdx.y;
    int t  = threadIdx.x;
    const float4* v4 = (const float4*)(value + ((size_t)bn * C_ + c) * HW_);
    const float4* m4 = (const float4*)(mask + (size_t)bn * HW_);
    float ws = 0.f, vs = 0.f, ms = 0.f;
    #pragma unroll
    for (int i = 0; i < 9; i++) {                          // 9216/4/256 = 9
        float4 v = v4[i * 256 + t];
        float4 m = m4[i * 256 + t];
        ws += v.x * m.x + v.y * m.y + v.z * m.z + v.w * m.w;
        vs += v.x + v.y + v.z + v.w;
        ms += m.x + m.y + m.z + m.w;
    }
    ws = warpSum(ws); vs = warpSum(vs);
    __shared__ float sw[8], sv[8], sm[8];
    if ((t & 31) == 0) { sw[t >> 5] = ws; sv[t >> 5] = vs; }
    if (c == 0) {
        ms = warpSum(ms);
        if ((t & 31) == 0) sm[t >> 5] = ms;
    }
    __syncthreads();
    if (t == 0) {
        float a = 0.f, b = 0.f;
        #pragma unroll
        for (int i = 0; i < 8; i++) { a += sw[i]; b += sv[i]; }
        d_wsum[bn * C_ + c] = a;
        d_vsum[bn * C_ + c] = b;
        if (c == 0) {
            float r = 0.f;
            #pragma unroll
            for (int i = 0; i < 8; i++) r += sm[i];
            d_msum[bn] = r;
        }
    }
}

// ---------------- kernel 2: policy + bank update ----------------------------
// grid 16, 256 threads. Warp w owns slot w.
__global__ void __launch_bounds__(256) k_policy(const float* __restrict__ proto,
                                                const float* __restrict__ age,
                                                const float* __restrict__ usage,
                                                const float* __restrict__ conf,
                                                const void* __restrict__ valid) {
    int bn = blockIdx.x, t = threadIdx.x;
    int w = t >> 5, l = t & 31;
    __shared__ float s_cand[C_], s_sim[K_], s_red[8], s_redU[8];
    __shared__ float s_vldf[K_], s_am, s_um;
    __shared__ int s_mode;
    __shared__ int s_upd, s_act;

    // valid dtype sniff + global age/usage maxes
    if (t == 0) {
        const unsigned int* wd = (const unsigned int*)valid;
        int isInt = 1, isFlt = 1;
        for (int i = 0; i < 32; i++) {
            unsigned int x = wd[i];
            isInt &= (x <= 1u);
            isFlt &= (x == 0u || x == 0x3f800000u);
        }
        s_mode = isInt ? 1 : (isFlt ? 2 : 0);
    }
    {
        float a = (t < 128) ? age[t]   : -1e30f;
        float u = (t < 128) ? usage[t] : -1e30f;
        a = warpMax(a); u = warpMax(u);
        if (l == 0) { s_red[w] = a; s_redU[w] = u; }
    }
    __syncthreads();
    if (t == 0) {
        float A = -1e30f, U = -1e30f;
        #pragma unroll
        for (int i = 0; i < 8; i++) { A = fmaxf(A, s_red[i]); U = fmaxf(U, s_redU[i]); }
        s_am = fmaxf(A, 1.0f); s_um = fmaxf(U, 1.0f);
    }
    __syncthreads();              // s_mode visible before decode
    if (t < K_) {
        int idx = bn * K_ + t, v;
        if (s_mode == 1)      v = ((const int*)valid)[idx] != 0;
        else if (s_mode == 2) v = ((const float*)valid)[idx] != 0.0f;
        else                  v = ((const unsigned char*)valid)[idx] != 0;
        s_vldf[t] = v ? 1.0f : 0.0f;
    }
    __syncthreads();

    // candidate prototype (channel t), l2-normalized
    float msum = d_msum[bn];
    float cc = (msum <= 1e-5f)
             ? d_vsum[bn * C_ + t] * (1.0f / (float)HW_)
             : d_wsum[bn * C_ + t] / fmaxf(msum, 1e-6f);
    float ss = warpSum(cc * cc);
    if (l == 0) s_red[w] = ss;
    __syncthreads();
    float tot = 0.f;
    #pragma unroll
    for (int i = 0; i < 8; i++) tot += s_red[i];
    float cn = cc / fmaxf(sqrtf(tot), 1e-12f);
    s_cand[t] = cn;
    __syncthreads();

    // sim[k]: warp w handles slot w
    const float* pbase = proto + (size_t)bn * K_ * C_;
    {
        float ps = 0.f, pd = 0.f;
        #pragma unroll
        for (int i = 0; i < 8; i++) {
            float p = pbase[w * C_ + i * 32 + l];
            ps += p * p;
            pd += p * s_cand[i * 32 + l];
        }
        ps = warpSum(ps); pd = warpSum(pd);
        if (l == 0) {
            float sim = pd / fmaxf(sqrtf(ps), 1e-12f);
            s_sim[w] = (s_vldf[w] > 0.5f) ? sim : -1.0f;
        }
    }
    __syncthreads();

    // decision (thread 0)
    if (t == 0) {
        bool v[K_]; bool anyv = false, anyi = false;
        #pragma unroll
        for (int k = 0; k < K_; k++) {
            v[k] = (s_vldf[k] > 0.5f);
            anyv |= v[k]; anyi |= !v[k];
        }
        float best = -1e30f; int tgt = 0;
        #pragma unroll
        for (int k = 0; k < K_; k++) if (s_sim[k] > best) { best = s_sim[k]; tgt = k; }
        int target = anyv ? tgt : 0;
        float msim = anyv ? s_sim[target] : -1.0f;
        int action = (!anyv) ? 3 : ((msim >= 0.8f) ? 1 : ((msim >= 0.3f) ? 0 : 3));
        float bs = -1e30f; int vic = 0;
        #pragma unroll
        for (int k = 0; k < K_; k++) {
            float sc = age[bn * K_ + k] / s_am
                     + (1.0f - usage[bn * K_ + k] / s_um)
                     + (1.0f - conf[bn * K_ + k]);
            if (sc > bs) { bs = sc; vic = k; }
        }
        int fe = 0;
        for (int k = 0; k < K_; k++) { if (!v[k]) { fe = k; break; } }
        int spawn = anyi ? fe : vic;
        s_upd = (action == 1) ? target : spawn;
        s_act = (action == 1) ? 1 : ((action == 3) ? 2 : 0);  // 1=refine, 2=spawn
        d_anyv[bn] = (anyv || action == 3) ? 1 : 0;
    }
    __syncthreads();
    int upd = s_upd, mode = s_act;

    // per-warp slot update: warp w owns slot w
    {
        float pn[8]; float q = 0.f;
        #pragma unroll
        for (int i = 0; i < 8; i++) {
            float p = pbase[w * C_ + i * 32 + l];
            float x = p;
            if (w == upd) {
                if (mode == 1)      x = 0.7f * p + 0.3f * s_cand[i * 32 + l];
                else if (mode == 2) x = s_cand[i * 32 + l];
            }
            pn[i] = x; q += x * x;
        }
        q = warpSum(q);
        float nrm = fmaxf(sqrtf(q), 1e-12f);
        float inv = 1.0f / nrm;
        size_t o = (size_t)bn * K_ * C_ + (size_t)w * C_;
        bool storeNorm = (w == upd && mode == 1);   // refine slot stores normalized
        #pragma unroll
        for (int i = 0; i < 8; i++)
            d_bnn[o + i * 32 + l] = pn[i] * inv;
        if (l == 0) {
            d_pscale[bn * K_ + w] = storeNorm ? 1.0f : nrm;
            bool vk = (s_vldf[w] > 0.5f);
            d_vldn[bn * K_ + w] = (vk || (mode == 2 && w == upd)) ? 1.0f : 0.0f;
        }
    }
}

// ---------------- kernel 3: register-resident fused readout -----------------
// grid (HW/32, N, B) = 4608 blocks, 256 threads, ~19KB smem, 2 blocks/SM.
// Thread = (pixel quad col 0..7, channel residue g 0..31). Value loaded ONCE
// into registers (16 batched LDG.128) and reused for both rsim and blend; no
// smem tile. The only DRAM-idle window is the small reduction+softmax.
#define FMA4(acc, s, vv) do { \
    (acc).x += (s) * (vv).x; (acc).y += (s) * (vv).y; \
    (acc).z += (s) * (vv).z; (acc).w += (s) * (vv).w; } while (0)

__device__ __forceinline__ void red4(float4& a) {
    #pragma unroll
    for (int o = 16; o >= 8; o >>= 1) {
        a.x += __shfl_down_sync(0xffffffffu, a.x, o);
        a.y += __shfl_down_sync(0xffffffffu, a.y, o);
        a.z += __shfl_down_sync(0xffffffffu, a.z, o);
        a.w += __shfl_down_sync(0xffffffffu, a.w, o);
    }
}

__global__ void __launch_bounds__(256, 2) k_readout(const float* __restrict__ value,
                                                    const float* __restrict__ frame,
                                                    const float* __restrict__ pgate,
                                                    const float* __restrict__ fgate,
                                                    float* __restrict__ out) {
    __shared__ float s_bnnT[C_][K_];     // [c][k], 8 KB
    __shared__ float s_part[8][8][36];   // [warp][col][ns4 | r[8]x4], 9 KB
    __shared__ float s_rsim[PX_][K_];
    __shared__ float s_ns[PX_];
    __shared__ float s_attn[PX_][K_];    // a[k] * pscale[k]
    __shared__ float s_vld[K_], s_psc[K_];
    __shared__ int s_any;

    int tile = blockIdx.x, n = blockIdx.y, b = blockIdx.z;
    int bn = b * N_ + n;
    int t = threadIdx.x;
    int col = t & 7, g = t >> 3;         // pixel quad, channel residue
    int w = t >> 5, lane = t & 31;
    int pix0 = tile * PX_;

    // ---- batched value loads (one DRAM touch, held in regs) ----------------
    const float* vb = value + (size_t)bn * C_ * HW_ + pix0 + col * 4;
    float4 v[8];
    #pragma unroll
    for (int i = 0; i < 8; i++)
        v[i] = *(const float4*)(vb + (size_t)(g + 32 * i) * HW_);

    // ---- prototypes (transposed) + flags (L2) ------------------------------
    const size_t off = (size_t)bn * K_ * C_;
    #pragma unroll
    for (int i = 0; i < 8; i++) {
        int j = i * 256 + t;             // j = k*C + c
        s_bnnT[j & 255][j >> 8] = d_bnn[off + j];
    }
    if (t < K_) { s_vld[t] = d_vldn[bn * K_ + t]; s_psc[t] = d_pscale[bn * K_ + t]; }
    if (t == 0) s_any = d_anyv[bn];
    __syncthreads();

    // ---- phase A: rsim + ||v||^2 partials over this thread's 8 channels ----
    float4 ns = make_float4(0.f, 0.f, 0.f, 0.f);
    float4 r[K_];
    #pragma unroll
    for (int k = 0; k < K_; k++) r[k] = make_float4(0.f, 0.f, 0.f, 0.f);
    #pragma unroll
    for (int i = 0; i < 8; i++) {
        int c = g + 32 * i;
        float4 vv = v[i];
        FMA4(ns, vv.x, vv); ns.x = ns.x;   // ns += vv*vv done below properly
    }
    // redo cleanly (avoid macro misuse): accumulate ns and r
    ns = make_float4(0.f, 0.f, 0.f, 0.f);
    #pragma unroll
    for (int k = 0; k < K_; k++) r[k] = make_float4(0.f, 0.f, 0.f, 0.f);
    #pragma unroll
    for (int i = 0; i < 8; i++) {
        int c = g + 32 * i;
        float4 vv = v[i];
        ns.x += vv.x * vv.x; ns.y += vv.y * vv.y;
        ns.z += vv.z * vv.z; ns.w += vv.w * vv.w;
        float4 b0 = *(const float4*)&s_bnnT[c][0];
        float4 b1 = *(const float4*)&s_bnnT[c][4];
        FMA4(r[0], b0.x, vv); FMA4(r[1], b0.y, vv);
        FMA4(r[2], b0.z, vv); FMA4(r[3], b0.w, vv);
        FMA4(r[4], b1.x, vv); FMA4(r[5], b1.y, vv);
        FMA4(r[6], b1.z, vv); FMA4(r[7], b1.w, vv);
    }

    // ---- phase B: reduce the 4 g-subgroups within each warp ----------------
    red4(ns);
    #pragma unroll
    for (int k = 0; k < K_; k++) red4(r[k]);
    if (lane < 8) {                       // lane == col here
        float* pp = &s_part[w][lane][0];
        pp[0] = ns.x; pp[1] = ns.y; pp[2] = ns.z; pp[3] = ns.w;
        #pragma unroll
        for (int k = 0; k < K_; k++) {
            pp[4 + 4 * k + 0] = r[k].x; pp[4 + 4 * k + 1] = r[k].y;
            pp[4 + 4 * k + 2] = r[k].z; pp[4 + 4 * k + 3] = r[k].w;
        }
    }
    __syncthreads();

    // ---- phase C: cross-warp reduce + per-pixel softmax --------------------
    {
        int px = t & 31, item = t >> 5;   // item = slot k
        float rv = 0.f;
        #pragma unroll
        for (int ww = 0; ww < 8; ww++)
            rv += s_part[ww][px >> 2][4 + 4 * item + (px & 3)];
        s_rsim[px][item] = rv;
        if (item == 0) {
            float nv = 0.f;
            #pragma unroll
            for (int ww = 0; ww < 8; ww++)
                nv += s_part[ww][px >> 2][px & 3];
            s_ns[px] = nv;
        }
    }
    __syncthreads();
    if (t < PX_) {
        float inv = 1.0f / fmaxf(sqrtf(s_ns[t]), 1e-12f);
        float a[K_];
        if (!s_any) {
            #pragma unroll
            for (int k = 0; k < K_; k++) a[k] = 0.f;
        } else {
            float m = -1e30f;
            #pragma unroll
            for (int k = 0; k < K_; k++)
                if (s_vld[k] > 0.5f) m = fmaxf(m, s_rsim[t][k] * inv);
            float tot = 0.f;
            #pragma unroll
            for (int k = 0; k < K_; k++) {
                float e = (s_vld[k] > 0.5f) ? __expf(s_rsim[t][k] * inv - m) : 0.f;
                a[k] = e; tot += e;
            }
            float z = 1.0f / tot;
            #pragma unroll
            for (int k = 0; k < K_; k++) a[k] *= z;
        }
        #pragma unroll
        for (int k = 0; k < K_; k++) s_attn[t][k] = a[k] * s_psc[k];
    }
    __syncthreads();

    // ---- phase D: blend from registers + store -----------------------------
    {
        float4 Aa[4], Ab[4];
        #pragma unroll
        for (int j = 0; j < 4; j++) {
            Aa[j] = *(const float4*)&s_attn[col * 4 + j][0];
            Ab[j] = *(const float4*)&s_attn[col * 4 + j][4];
        }
        float pg = *pgate, fg = *fgate;
        const float* fb = frame + (size_t)b * C_ * HW_ + pix0 + col * 4;
        float* ob = out + (size_t)bn * C_ * HW_ + pix0 + col * 4;
        float4 f[8];
        #pragma unroll
        for (int i = 0; i < 8; i++)
            f[i] = *(const float4*)(fb + (size_t)(g + 32 * i) * HW_);
        #pragma unroll
        for (int i = 0; i < 8; i++) {
            int c = g + 32 * i;
            float4 b0 = *(const float4*)&s_bnnT[c][0];
            float4 b1 = *(const float4*)&s_bnnT[c][4];
            float4 pm;
            pm.x = Aa[0].x * b0.x + Aa[0].y * b0.y + Aa[0].z * b0.z + Aa[0].w * b0.w
                 + Ab[0].x * b1.x + Ab[0].y * b1.y + Ab[0].z * b1.z + Ab[0].w * b1.w;
            pm.y = Aa[1].x * b0.x + Aa[1].y * b0.y + Aa[1].z * b0.z + Aa[1].w * b0.w
                 + Ab[1].x * b1.x + Ab[1].y * b1.y + Ab[1].z * b1.z + Ab[1].w * b1.w;
            pm.z = Aa[2].x * b0.x + Aa[2].y * b0.y + Aa[2].z * b0.z + Aa[2].w * b0.w
                 + Ab[2].x * b1.x + Ab[2].y * b1.y + Ab[2].z * b1.z + Ab[2].w * b1.w;
            pm.w = Aa[3].x * b0.x + Aa[3].y * b0.y + Aa[3].z * b0.z + Aa[3].w * b0.w
                 + Ab[3].x * b1.x + Ab[3].y * b1.y + Ab[3].z * b1.z + Ab[3].w * b1.w;
            float4 o;
            o.x = v[i].x + pg * pm.x + fg * f[i].x;
            o.y = v[i].y + pg * pm.y + fg * f[i].y;
            o.z = v[i].z + pg * pm.z + fg * f[i].z;
            o.w = v[i].w + pg * pm.w + fg * f[i].w;
            *(float4*)(ob + (size_t)c * HW_) = o;
        }
    }
}

// ---------------- launch ----------------------------------------------------
extern "C" void kernel_launch(void* const* d_in, const int* in_sizes, int n_in,
                              void* d_out, int out_size) {
    const float* value = (const float*)d_in[0];
    const float* frame = (const float*)d_in[1];
    const float* mask  = (const float*)d_in[2];
    const float* proto = (const float*)d_in[3];
    const float* age   = (const float*)d_in[4];
    const float* usage = (const float*)d_in[5];
    const float* conf  = (const float*)d_in[6];
    // d_in[7..10] = W1, b1, W2, b2: dead code (logits unused by the output)
    const float* pgate = (const float*)d_in[11];
    const float* fgate = (const float*)d_in[12];
    const void*  valid = (const void*)d_in[13];
    float* out = (float*)d_out;

    dim3 gc(C_, N_, B_);
    k_candsum<<<gc, 256>>>(value, mask);
    k_policy<<<BN_, 256>>>(proto, age, usage, conf, valid);
    dim3 gr(HW_ / PX_, N_, B_);
    k_readout<<<gr, 256>>>(value, frame, pgate, fgate, out);
}

// round 14
// speedup vs baseline: 1.6861x; 1.6861x over previous
#include <cuda_runtime.h>
#include <math.h>

#define B_  2
#define N_  8
#define K_  8
#define C_  256
#define HW_ 9216
#define BN_ (B_*N_)
#define PX_ 32                      // pixels per readout tile

// ---------------- scratch (__device__ globals: no allocation allowed) -------
__device__ float d_wsum[BN_*C_];       // sum(value*mask) over HW
__device__ float d_vsum[BN_*C_];       // sum(value) over HW
__device__ float d_msum[BN_];          // sum(mask) over HW
__device__ float d_bnn [BN_*K_*C_];    // l2norm(proto_new)
__device__ float d_pscale[BN_*K_];     // proto_new = bnn * pscale
__device__ float d_vldn[BN_*K_];       // valid_new as float
__device__ int   d_anyv[BN_];          // any(valid_new)

__device__ __forceinline__ float warpSum(float v) {
    #pragma unroll
    for (int o = 16; o; o >>= 1) v += __shfl_xor_sync(0xffffffffu, v, o);
    return v;
}
__device__ __forceinline__ float warpMax(float v) {
    #pragma unroll
    for (int o = 16; o; o >>= 1) v = fmaxf(v, __shfl_xor_sync(0xffffffffu, v, o));
    return v;
}

// ---------------- kernel 1: masked pooling sums over HW (+ msum) -----------
// grid (C, N, B), 256 threads. Reads full value once (~5.3 TB/s measured).
__global__ void __launch_bounds__(256) k_candsum(const float* __restrict__ value,
                                                 const float* __restrict__ mask) {
    int c  = blockIdx.x;
    int bn = blockIdx.z * N_ + blockIdx.y;
    int t  = threadIdx.x;
    const float4* v4 = (const float4*)(value + ((size_t)bn * C_ + c) * HW_);
    const float4* m4 = (const float4*)(mask + (size_t)bn * HW_);
    float ws = 0.f, vs = 0.f, ms = 0.f;
    #pragma unroll
    for (int i = 0; i < 9; i++) {                          // 9216/4/256 = 9
        float4 v = v4[i * 256 + t];
        float4 m = m4[i * 256 + t];
        ws += v.x * m.x + v.y * m.y + v.z * m.z + v.w * m.w;
        vs += v.x + v.y + v.z + v.w;
        ms += m.x + m.y + m.z + m.w;
    }
    ws = warpSum(ws); vs = warpSum(vs);
    __shared__ float sw[8], sv[8], sm[8];
    if ((t & 31) == 0) { sw[t >> 5] = ws; sv[t >> 5] = vs; }
    if (c == 0) {
        ms = warpSum(ms);
        if ((t & 31) == 0) sm[t >> 5] = ms;
    }
    __syncthreads();
    if (t == 0) {
        float a = 0.f, b = 0.f;
        #pragma unroll
        for (int i = 0; i < 8; i++) { a += sw[i]; b += sv[i]; }
        d_wsum[bn * C_ + c] = a;
        d_vsum[bn * C_ + c] = b;
        if (c == 0) {
            float r = 0.f;
            #pragma unroll
            for (int i = 0; i < 8; i++) r += sm[i];
            d_msum[bn] = r;
        }
    }
}

// ---------------- kernel 2: policy + bank update ----------------------------
// grid 16, 256 threads. Warp w owns slot w.
__global__ void __launch_bounds__(256) k_policy(const float* __restrict__ proto,
                                                const float* __restrict__ age,
                                                const float* __restrict__ usage,
                                                const float* __restrict__ conf,
                                                const void* __restrict__ valid) {
    int bn = blockIdx.x, t = threadIdx.x;
    int w = t >> 5, l = t & 31;
    __shared__ float s_cand[C_], s_sim[K_], s_red[8], s_redU[8];
    __shared__ float s_vldf[K_], s_am, s_um;
    __shared__ int s_mode;
    __shared__ int s_upd, s_act;

    // valid dtype sniff + global age/usage maxes
    if (t == 0) {
        const unsigned int* wd = (const unsigned int*)valid;
        int isInt = 1, isFlt = 1;
        for (int i = 0; i < 32; i++) {
            unsigned int x = wd[i];
            isInt &= (x <= 1u);
            isFlt &= (x == 0u || x == 0x3f800000u);
        }
        s_mode = isInt ? 1 : (isFlt ? 2 : 0);
    }
    {
        float a = (t < 128) ? age[t]   : -1e30f;
        float u = (t < 128) ? usage[t] : -1e30f;
        a = warpMax(a); u = warpMax(u);
        if (l == 0) { s_red[w] = a; s_redU[w] = u; }
    }
    __syncthreads();
    if (t == 0) {
        float A = -1e30f, U = -1e30f;
        #pragma unroll
        for (int i = 0; i < 8; i++) { A = fmaxf(A, s_red[i]); U = fmaxf(U, s_redU[i]); }
        s_am = fmaxf(A, 1.0f); s_um = fmaxf(U, 1.0f);
    }
    __syncthreads();              // s_mode visible before decode
    if (t < K_) {
        int idx = bn * K_ + t, v;
        if (s_mode == 1)      v = ((const int*)valid)[idx] != 0;
        else if (s_mode == 2) v = ((const float*)valid)[idx] != 0.0f;
        else                  v = ((const unsigned char*)valid)[idx] != 0;
        s_vldf[t] = v ? 1.0f : 0.0f;
    }
    __syncthreads();

    // candidate prototype (channel t), l2-normalized
    float msum = d_msum[bn];
    float cc = (msum <= 1e-5f)
             ? d_vsum[bn * C_ + t] * (1.0f / (float)HW_)
             : d_wsum[bn * C_ + t] / fmaxf(msum, 1e-6f);
    float ss = warpSum(cc * cc);
    if (l == 0) s_red[w] = ss;
    __syncthreads();
    float tot = 0.f;
    #pragma unroll
    for (int i = 0; i < 8; i++) tot += s_red[i];
    float cn = cc / fmaxf(sqrtf(tot), 1e-12f);
    s_cand[t] = cn;
    __syncthreads();

    // sim[k]: warp w handles slot w
    const float* pbase = proto + (size_t)bn * K_ * C_;
    {
        float ps = 0.f, pd = 0.f;
        #pragma unroll
        for (int i = 0; i < 8; i++) {
            float p = pbase[w * C_ + i * 32 + l];
            ps += p * p;
            pd += p * s_cand[i * 32 + l];
        }
        ps = warpSum(ps); pd = warpSum(pd);
        if (l == 0) {
            float sim = pd / fmaxf(sqrtf(ps), 1e-12f);
            s_sim[w] = (s_vldf[w] > 0.5f) ? sim : -1.0f;
        }
    }
    __syncthreads();

    // decision (thread 0)
    if (t == 0) {
        bool v[K_]; bool anyv = false, anyi = false;
        #pragma unroll
        for (int k = 0; k < K_; k++) {
            v[k] = (s_vldf[k] > 0.5f);
            anyv |= v[k]; anyi |= !v[k];
        }
        float best = -1e30f; int tgt = 0;
        #pragma unroll
        for (int k = 0; k < K_; k++) if (s_sim[k] > best) { best = s_sim[k]; tgt = k; }
        int target = anyv ? tgt : 0;
        float msim = anyv ? s_sim[target] : -1.0f;
        int action = (!anyv) ? 3 : ((msim >= 0.8f) ? 1 : ((msim >= 0.3f) ? 0 : 3));
        float bs = -1e30f; int vic = 0;
        #pragma unroll
        for (int k = 0; k < K_; k++) {
            float sc = age[bn * K_ + k] / s_am
                     + (1.0f - usage[bn * K_ + k] / s_um)
                     + (1.0f - conf[bn * K_ + k]);
            if (sc > bs) { bs = sc; vic = k; }
        }
        int fe = 0;
        for (int k = 0; k < K_; k++) { if (!v[k]) { fe = k; break; } }
        int spawn = anyi ? fe : vic;
        s_upd = (action == 1) ? target : spawn;
        s_act = (action == 1) ? 1 : ((action == 3) ? 2 : 0);  // 1=refine, 2=spawn
        d_anyv[bn] = (anyv || action == 3) ? 1 : 0;
    }
    __syncthreads();
    int upd = s_upd, mode = s_act;

    // per-warp slot update: warp w owns slot w
    {
        float pn[8]; float q = 0.f;
        #pragma unroll
        for (int i = 0; i < 8; i++) {
            float p = pbase[w * C_ + i * 32 + l];
            float x = p;
            if (w == upd) {
                if (mode == 1)      x = 0.7f * p + 0.3f * s_cand[i * 32 + l];
                else if (mode == 2) x = s_cand[i * 32 + l];
            }
            pn[i] = x; q += x * x;
        }
        q = warpSum(q);
        float nrm = fmaxf(sqrtf(q), 1e-12f);
        float inv = 1.0f / nrm;
        size_t o = (size_t)bn * K_ * C_ + (size_t)w * C_;
        bool storeNorm = (w == upd && mode == 1);   // refine slot stores normalized
        #pragma unroll
        for (int i = 0; i < 8; i++)
            d_bnn[o + i * 32 + l] = pn[i] * inv;
        if (l == 0) {
            d_pscale[bn * K_ + w] = storeNorm ? 1.0f : nrm;
            bool vk = (s_vldf[w] > 0.5f);
            d_vldn[bn * K_ + w] = (vk || (mode == 2 && w == upd)) ? 1.0f : 0.0f;
        }
    }
}

// ---------------- kernel 3: fused readout, small smem tile (4 blocks/SM) ----
// grid (HW/32, N, B) = 4608 blocks, 256 threads, ~50KB dynamic smem.
// 4 blocks/SM * 8 warps = 32 warps. Value staged ONCE; both scans from smem.
// Thread = (pixel px 0..31, channel octant q 0..7, 32 channels each).
// smem layout (floats):
//   tile [C][PX]            0      .. 8192
//   bnnT [C][8]             8192   .. 10240
//   part [8][PX][9]         10240  .. 12544
//   attn [PX][8]            12544  .. 12800
//   vld  [8]                12800  .. 12808
//   psc  [8]                12808  .. 12816
#define SM_TILE 0
#define SM_BNN  8192
#define SM_PART 10240
#define SM_ATTN 12544
#define SM_VLD  12800
#define SM_PSC  12808
#define SM_FLOATS 12816

__global__ void __launch_bounds__(256) k_readout(const float* __restrict__ value,
                                                 const float* __restrict__ frame,
                                                 const float* __restrict__ pgate,
                                                 const float* __restrict__ fgate,
                                                 float* __restrict__ out) {
    extern __shared__ float smf[];
    __shared__ int s_any;
    int tile = blockIdx.x, n = blockIdx.y, b = blockIdx.z;
    int bn = b * N_ + n;
    int t = threadIdx.x;
    int px = t & 31, q = t >> 5;         // pixel lane (0..31), channel octant (0..7)
    int pix0 = tile * PX_;

    // ---- stage value tile: 256 rows x 32 px, coalesced float4 rows ---------
    const float* vbase = value + (size_t)bn * C_ * HW_ + pix0;
    #pragma unroll
    for (int i = 0; i < 8; i++) {
        int j = i * 256 + t;             // 2048 float4 chunks
        int row = j >> 3, col = j & 7;   // 8 float4 per row
        float4 v = *(const float4*)(vbase + (size_t)row * HW_ + col * 4);
        *(float4*)&smf[SM_TILE + row * PX_ + col * 4] = v;
    }
    // ---- prototypes (transposed) + flags (L2) ------------------------------
    const size_t off = (size_t)bn * K_ * C_;
    #pragma unroll
    for (int i = 0; i < 8; i++) {
        int j = i * 256 + t;             // j = k*C + c
        smf[SM_BNN + (j & 255) * 8 + (j >> 8)] = d_bnn[off + j];
    }
    if (t < K_) {
        smf[SM_VLD + t] = d_vldn[bn * K_ + t];
        smf[SM_PSC + t] = d_pscale[bn * K_ + t];
    }
    if (t == 0) s_any = d_anyv[bn];
    __syncthreads();

    // ---- scan 1: partial rsim + ||v||^2 over this thread's 32 channels -----
    {
        float r[K_]; float ns = 0.f;
        #pragma unroll
        for (int k = 0; k < K_; k++) r[k] = 0.f;
        int cbase = q * 32;
        #pragma unroll 8
        for (int ci = 0; ci < 32; ci++) {
            int c = cbase + ci;
            float v = smf[SM_TILE + c * PX_ + px];
            ns += v * v;
            float4 b0 = *(const float4*)&smf[SM_BNN + c * 8];
            float4 b1 = *(const float4*)&smf[SM_BNN + c * 8 + 4];
            r[0] += b0.x * v; r[1] += b0.y * v; r[2] += b0.z * v; r[3] += b0.w * v;
            r[4] += b1.x * v; r[5] += b1.y * v; r[6] += b1.z * v; r[7] += b1.w * v;
        }
        float* pp = &smf[SM_PART + (q * PX_ + px) * 9];
        pp[0] = ns;
        #pragma unroll
        for (int k = 0; k < K_; k++) pp[1 + k] = r[k];
    }
    __syncthreads();

    // ---- per-pixel softmax (threads 0..31), pscale folded in ---------------
    if (t < PX_) {
        float ns = 0.f, r[K_];
        #pragma unroll
        for (int k = 0; k < K_; k++) r[k] = 0.f;
        #pragma unroll
        for (int qq = 0; qq < 8; qq++) {
            const float* pp = &smf[SM_PART + (qq * PX_ + t) * 9];
            ns += pp[0];
            #pragma unroll
            for (int k = 0; k < K_; k++) r[k] += pp[1 + k];
        }
        float inv = 1.0f / fmaxf(sqrtf(ns), 1e-12f);
        float a[K_];
        if (!s_any) {
            #pragma unroll
            for (int k = 0; k < K_; k++) a[k] = 0.f;
        } else {
            float m = -1e30f;
            #pragma unroll
            for (int k = 0; k < K_; k++)
                if (smf[SM_VLD + k] > 0.5f) m = fmaxf(m, r[k] * inv);
            float tot = 0.f;
            #pragma unroll
            for (int k = 0; k < K_; k++) {
                float e = (smf[SM_VLD + k] > 0.5f) ? __expf(r[k] * inv - m) : 0.f;
                a[k] = e; tot += e;
            }
            float z = 1.0f / tot;
            #pragma unroll
            for (int k = 0; k < K_; k++) a[k] *= z;
        }
        #pragma unroll
        for (int k = 0; k < K_; k++)
            smf[SM_ATTN + t * 8 + k] = a[k] * smf[SM_PSC + k];  // fold pscale
    }
    __syncthreads();

    // ---- scan 2: blend + store (value from smem, frame GMEM/L2) ------------
    {
        float4 A0 = *(const float4*)&smf[SM_ATTN + px * 8];
        float4 A1 = *(const float4*)&smf[SM_ATTN + px * 8 + 4];
        float pg = *pgate, fg = *fgate;
        const float* fbase = frame + (size_t)b * C_ * HW_ + pix0 + px;
        float* obase = out + (size_t)bn * C_ * HW_ + pix0 + px;
        int cbase = q * 32;
        #pragma unroll 8
        for (int ci = 0; ci < 32; ci++) {
            int c = cbase + ci;
            float v = smf[SM_TILE + c * PX_ + px];
            float f = fbase[(size_t)c * HW_];
            float4 p0 = *(const float4*)&smf[SM_BNN + c * 8];
            float4 p1 = *(const float4*)&smf[SM_BNN + c * 8 + 4];
            float pm = A0.x * p0.x + A0.y * p0.y + A0.z * p0.z + A0.w * p0.w
                     + A1.x * p1.x + A1.y * p1.y + A1.z * p1.z + A1.w * p1.w;
            obase[(size_t)c * HW_] = v + pg * pm + fg * f;
        }
    }
}

// ---------------- launch ----------------------------------------------------
extern "C" void kernel_launch(void* const* d_in, const int* in_sizes, int n_in,
                              void* d_out, int out_size) {
    const float* value = (const float*)d_in[0];
    const float* frame = (const float*)d_in[1];
    const float* mask  = (const float*)d_in[2];
    const float* proto = (const float*)d_in[3];
    const float* age   = (const float*)d_in[4];
    const float* usage = (const float*)d_in[5];
    const float* conf  = (const float*)d_in[6];
    // d_in[7..10] = W1, b1, W2, b2: dead code (logits unused by the output)
    const float* pgate = (const float*)d_in[11];
    const float* fgate = (const float*)d_in[12];
    const void*  valid = (const void*)d_in[13];
    float* out = (float*)d_out;

    const int smemBytes = SM_FLOATS * sizeof(float);   // ~50 KB
    cudaFuncSetAttribute(k_readout, cudaFuncAttributeMaxDynamicSharedMemorySize,
                         smemBytes);

    dim3 gc(C_, N_, B_);
    k_candsum<<<gc, 256>>>(value, mask);
    k_policy<<<BN_, 256>>>(proto, age, usage, conf, valid);
    dim3 gr(HW_ / PX_, N_, B_);
    k_readout<<<gr, 256, smemBytes>>>(value, frame, pgate, fgate, out);
}